// round 1
// baseline (speedup 1.0000x reference)
#include <cuda_runtime.h>
#include <math.h>

#define H    128
#define KNB  48
#define LSEQ 2048
#define NTOK_MAX 4096

// Scratch (static device globals — no allocation allowed)
__device__ float g_P1 [NTOK_MAX * H];
__device__ float g_P3 [NTOK_MAX * H];
__device__ float g_HV1[NTOK_MAX * H];
__device__ float g_P11[NTOK_MAX * H];
__device__ float g_P13[NTOK_MAX * H];

__device__ __forceinline__ float gelu_f(float x) {
    return 0.5f * x * (1.0f + erff(x * 0.70710678118654752f));
}

// acc[ROWS] += A[ROWS][K4*4] (smem, row-major) @ W[:, n]  (W row-major k x ldw)
template<int ROWS, int K4>
__device__ __forceinline__ void gemm_acc(float* acc, const float* A,
                                         const float* __restrict__ W,
                                         int n, int ldw) {
    const float4* A4 = reinterpret_cast<const float4*>(A);
    #pragma unroll 1
    for (int k4 = 0; k4 < K4; k4++) {
        const float* wp = W + (k4 * 4) * ldw + n;
        float w0 = wp[0];
        float w1 = wp[ldw];
        float w2 = wp[2 * ldw];
        float w3 = wp[3 * ldw];
        #pragma unroll
        for (int r = 0; r < ROWS; r++) {
            float4 a = A4[r * K4 + k4];   // warp-uniform address -> smem broadcast
            acc[r] = fmaf(a.x, w0, acc[r]);
            acc[r] = fmaf(a.y, w1, acc[r]);
            acc[r] = fmaf(a.z, w2, acc[r]);
            acc[r] = fmaf(a.w, w3, acc[r]);
        }
    }
}

// ---------------------------------------------------------------------------
// Kernel P: per-token precompute  P1 = hV @ W1a + b1,  P3 = hV @ W1c
// 32 tokens per block; W1a/W1c cached in smem (weights read once per block).
// ---------------------------------------------------------------------------
__global__ void __launch_bounds__(128) k_pre(const float* __restrict__ hV,
                                             const float* __restrict__ W1,
                                             const float* __restrict__ b1) {
    extern __shared__ float sm[];
    float* w1a  = sm;                // H*H
    float* w1c  = sm + H * H;        // H*H
    float* rows = sm + 2 * H * H;    // 32*H
    int tid = threadIdx.x;
    for (int i = tid; i < H * H; i += 128) {
        w1a[i] = W1[i];                   // rows 0..127   (center block)
        w1c[i] = W1[2 * H * H + i];       // rows 256..383 (neighbor block)
    }
    int t0 = blockIdx.x * 32;
    for (int i = tid; i < 32 * H; i += 128) rows[i] = hV[(size_t)t0 * H + i];
    __syncthreads();

    float bn = b1[tid];
    for (int r = 0; r < 32; r++) {
        float a1 = bn, a3 = 0.f;
        const float4* rv = reinterpret_cast<const float4*>(rows + r * H);
        #pragma unroll 8
        for (int k4 = 0; k4 < 32; k4++) {
            float4 v = rv[k4];
            int k = k4 * 4;
            a1 = fmaf(v.x, w1a[(k + 0) * H + tid], a1);
            a1 = fmaf(v.y, w1a[(k + 1) * H + tid], a1);
            a1 = fmaf(v.z, w1a[(k + 2) * H + tid], a1);
            a1 = fmaf(v.w, w1a[(k + 3) * H + tid], a1);
            a3 = fmaf(v.x, w1c[(k + 0) * H + tid], a3);
            a3 = fmaf(v.y, w1c[(k + 1) * H + tid], a3);
            a3 = fmaf(v.z, w1c[(k + 2) * H + tid], a3);
            a3 = fmaf(v.w, w1c[(k + 3) * H + tid], a3);
        }
        g_P1[(size_t)(t0 + r) * H + tid] = a1;
        g_P3[(size_t)(t0 + r) * H + tid] = a3;
    }
}

// ---------------------------------------------------------------------------
// Kernel A: node message MLP (48 edges per token), masked sum, residual + LN1
// One token per block; thread = output column; 48 edge rows in registers.
// ---------------------------------------------------------------------------
__global__ void __launch_bounds__(128, 3) k_node(
    const float* __restrict__ hV,  const float* __restrict__ hE,
    const int*   __restrict__ Eidx, const float* __restrict__ mattend,
    const float* __restrict__ W1,  const float* __restrict__ W2,
    const float* __restrict__ b2,  const float* __restrict__ W3,
    const float* __restrict__ b3,  const float* __restrict__ g1,
    const float* __restrict__ be1) {
    extern __shared__ float sm[];
    float* sE    = sm;                   // KNB*H : h_E rows
    float* sG    = sm + KNB * H;         // KNB*H : gathered P3, then layer2 out
    float* sBuf  = sm + 2 * KNB * H;     // KNB*H : layer1 out
    float* sP1   = sm + 3 * KNB * H;     // H
    float* sHV   = sP1 + H;              // H
    float* sMask = sHV + H;              // KNB
    float* sRed  = sMask + KNB;          // 8

    int tid = threadIdx.x;
    int t = blockIdx.x;
    int b = t / LSEQ;

    {   // load h_E tile
        const float4* src = reinterpret_cast<const float4*>(hE + (size_t)t * KNB * H);
        float4* dst = reinterpret_cast<float4*>(sE);
        for (int i = tid; i < KNB * H / 4; i += 128) dst[i] = src[i];
    }
    sP1[tid] = g_P1[(size_t)t * H + tid];
    sHV[tid] = hV [(size_t)t * H + tid];
    if (tid < KNB) sMask[tid] = mattend[(size_t)t * KNB + tid];
    {   // gather P3 rows of the 48 neighbors
        int warp = tid >> 5, lane = tid & 31;
        for (int r = warp; r < KNB; r += 4) {
            int idx = Eidx[(size_t)t * KNB + r];
            const float4* src = reinterpret_cast<const float4*>(g_P3 + (size_t)(b * LSEQ + idx) * H);
            reinterpret_cast<float4*>(sG + r * H)[lane] = src[lane];
        }
    }
    __syncthreads();

    float acc[KNB];
    // layer 1:  P1 + P3[gather] + hE @ W1b
    #pragma unroll
    for (int r = 0; r < KNB; r++) acc[r] = sP1[tid] + sG[r * H + tid];
    gemm_acc<KNB, 32>(acc, sE, W1 + H * H, tid, H);
    #pragma unroll
    for (int r = 0; r < KNB; r++) sBuf[r * H + tid] = gelu_f(acc[r]);
    __syncthreads();
    // layer 2
    {
        float bb = b2[tid];
        #pragma unroll
        for (int r = 0; r < KNB; r++) acc[r] = bb;
    }
    gemm_acc<KNB, 32>(acc, sBuf, W2, tid, H);
    #pragma unroll
    for (int r = 0; r < KNB; r++) sG[r * H + tid] = gelu_f(acc[r]);
    __syncthreads();
    // layer 3
    {
        float bb = b3[tid];
        #pragma unroll
        for (int r = 0; r < KNB; r++) acc[r] = bb;
    }
    gemm_acc<KNB, 32>(acc, sG, W3, tid, H);

    // masked sum over neighbors / 30, residual
    float dh = 0.f;
    #pragma unroll
    for (int r = 0; r < KNB; r++) dh = fmaf(sMask[r], acc[r], dh);
    float x = sHV[tid] + dh * (1.0f / 30.0f);

    // LayerNorm across the 128 threads
    float s = x, s2 = x * x;
    #pragma unroll
    for (int o = 16; o; o >>= 1) {
        s  += __shfl_xor_sync(0xffffffffu, s,  o);
        s2 += __shfl_xor_sync(0xffffffffu, s2, o);
    }
    if ((tid & 31) == 0) { sRed[tid >> 5] = s; sRed[4 + (tid >> 5)] = s2; }
    __syncthreads();
    s  = sRed[0] + sRed[1] + sRed[2] + sRed[3];
    s2 = sRed[4] + sRed[5] + sRed[6] + sRed[7];
    float m  = s * (1.f / H);
    float rs = rsqrtf(s2 * (1.f / H) - m * m + 1e-5f);
    g_HV1[(size_t)t * H + tid] = g1[tid] * (x - m) * rs + be1[tid];
}

// ---------------------------------------------------------------------------
// Kernel B: FFN (H->4H->H) + residual + LN2 + mask_V; also precompute
// P11 = hV2@W11a + b11 and P13 = hV2@W11c for the edge phase.
// 32 tokens per block.
// ---------------------------------------------------------------------------
__global__ void __launch_bounds__(128, 2) k_ffn(
    const float* __restrict__ maskV,
    const float* __restrict__ W_in,  const float* __restrict__ b_in,
    const float* __restrict__ W_out, const float* __restrict__ b_out,
    const float* __restrict__ g2,    const float* __restrict__ be2,
    const float* __restrict__ W11,   const float* __restrict__ b11,
    float* __restrict__ outV) {
    extern __shared__ float sm[];
    float* sX    = sm;               // 32*H
    float* sHid  = sm + 32 * H;      // 32*512
    float* sMask = sHid + 32 * 512;  // 32

    int tid = threadIdx.x;
    int t0 = blockIdx.x * 32;
    for (int i = tid; i < 32 * H; i += 128) sX[i] = g_HV1[(size_t)t0 * H + i];
    if (tid < 32) sMask[tid] = maskV[t0 + tid];
    __syncthreads();

    // hidden layer (512 cols, 4 chunks per thread)
    for (int c = 0; c < 4; c++) {
        int col = c * 128 + tid;
        float acc[32];
        float bi = b_in[col];
        #pragma unroll
        for (int r = 0; r < 32; r++) acc[r] = bi;
        gemm_acc<32, 32>(acc, sX, W_in, col, 512);
        #pragma unroll
        for (int r = 0; r < 32; r++) sHid[r * 512 + col] = gelu_f(acc[r]);
    }
    __syncthreads();

    // output layer + residual
    float acc[32];
    {
        float bo = b_out[tid];
        #pragma unroll
        for (int r = 0; r < 32; r++) acc[r] = bo;
    }
    gemm_acc<32, 128>(acc, sHid, W_out, tid, H);
    #pragma unroll
    for (int r = 0; r < 32; r++) acc[r] += sX[r * H + tid];
    __syncthreads();
    #pragma unroll
    for (int r = 0; r < 32; r++) sHid[r * H + tid] = acc[r];
    __syncthreads();

    // per-row LN + mask
    {
        int warp = tid >> 5, lane = tid & 31;
        for (int r = warp; r < 32; r += 4) {
            const float* row = sHid + r * H;
            float v[4] = { row[lane], row[lane + 32], row[lane + 64], row[lane + 96] };
            float s = v[0] + v[1] + v[2] + v[3];
            float s2 = v[0]*v[0] + v[1]*v[1] + v[2]*v[2] + v[3]*v[3];
            #pragma unroll
            for (int o = 16; o; o >>= 1) {
                s  += __shfl_xor_sync(0xffffffffu, s,  o);
                s2 += __shfl_xor_sync(0xffffffffu, s2, o);
            }
            float m  = s * (1.f / H);
            float rs = rsqrtf(s2 * (1.f / H) - m * m + 1e-5f);
            float mk = sMask[r];
            #pragma unroll
            for (int j = 0; j < 4; j++) {
                int n = lane + 32 * j;
                float y = mk * (g2[n] * (v[j] - m) * rs + be2[n]);
                outV[(size_t)(t0 + r) * H + n] = y;
                sX[r * H + n] = y;
            }
        }
    }
    __syncthreads();

    // P11 / P13 precompute for edge phase
    {
        float acc2[32];
        float bb = b11[tid];
        #pragma unroll
        for (int r = 0; r < 32; r++) acc2[r] = bb;
        gemm_acc<32, 32>(acc2, sX, W11, tid, H);
        #pragma unroll
        for (int r = 0; r < 32; r++) g_P11[(size_t)(t0 + r) * H + tid] = acc2[r];
        #pragma unroll
        for (int r = 0; r < 32; r++) acc2[r] = 0.f;
        gemm_acc<32, 32>(acc2, sX, W11 + 2 * H * H, tid, H);
        #pragma unroll
        for (int r = 0; r < 32; r++) g_P13[(size_t)(t0 + r) * H + tid] = acc2[r];
    }
}

// ---------------------------------------------------------------------------
// Kernel C: edge-update MLP + residual + per-edge LN3
// ---------------------------------------------------------------------------
__global__ void __launch_bounds__(128, 3) k_edge(
    const float* __restrict__ hE,  const int* __restrict__ Eidx,
    const float* __restrict__ W11, const float* __restrict__ W12,
    const float* __restrict__ b12, const float* __restrict__ W13,
    const float* __restrict__ b13, const float* __restrict__ g3,
    const float* __restrict__ be3, float* __restrict__ outE) {
    extern __shared__ float sm[];
    float* sE   = sm;                // KNB*H
    float* sG   = sm + KNB * H;      // KNB*H
    float* sBuf = sm + 2 * KNB * H;  // KNB*H
    float* sP   = sm + 3 * KNB * H;  // H

    int tid = threadIdx.x;
    int t = blockIdx.x;
    int b = t / LSEQ;

    {
        const float4* src = reinterpret_cast<const float4*>(hE + (size_t)t * KNB * H);
        float4* dst = reinterpret_cast<float4*>(sE);
        for (int i = tid; i < KNB * H / 4; i += 128) dst[i] = src[i];
    }
    sP[tid] = g_P11[(size_t)t * H + tid];
    {
        int warp = tid >> 5, lane = tid & 31;
        for (int r = warp; r < KNB; r += 4) {
            int idx = Eidx[(size_t)t * KNB + r];
            const float4* src = reinterpret_cast<const float4*>(g_P13 + (size_t)(b * LSEQ + idx) * H);
            reinterpret_cast<float4*>(sG + r * H)[lane] = src[lane];
        }
    }
    __syncthreads();

    float acc[KNB];
    #pragma unroll
    for (int r = 0; r < KNB; r++) acc[r] = sP[tid] + sG[r * H + tid];
    gemm_acc<KNB, 32>(acc, sE, W11 + H * H, tid, H);
    #pragma unroll
    for (int r = 0; r < KNB; r++) sBuf[r * H + tid] = gelu_f(acc[r]);
    __syncthreads();
    {
        float bb = b12[tid];
        #pragma unroll
        for (int r = 0; r < KNB; r++) acc[r] = bb;
    }
    gemm_acc<KNB, 32>(acc, sBuf, W12, tid, H);
    #pragma unroll
    for (int r = 0; r < KNB; r++) sG[r * H + tid] = gelu_f(acc[r]);
    __syncthreads();
    {
        float bb = b13[tid];
        #pragma unroll
        for (int r = 0; r < KNB; r++) acc[r] = bb;
    }
    gemm_acc<KNB, 32>(acc, sG, W13, tid, H);

    // x = h_E + msg
    #pragma unroll
    for (int r = 0; r < KNB; r++) sBuf[r * H + tid] = sE[r * H + tid] + acc[r];
    __syncthreads();

    // per-edge LN
    {
        int warp = tid >> 5, lane = tid & 31;
        for (int r = warp; r < KNB; r += 4) {
            const float* row = sBuf + r * H;
            float v[4] = { row[lane], row[lane + 32], row[lane + 64], row[lane + 96] };
            float s = v[0] + v[1] + v[2] + v[3];
            float s2 = v[0]*v[0] + v[1]*v[1] + v[2]*v[2] + v[3]*v[3];
            #pragma unroll
            for (int o = 16; o; o >>= 1) {
                s  += __shfl_xor_sync(0xffffffffu, s,  o);
                s2 += __shfl_xor_sync(0xffffffffu, s2, o);
            }
            float m  = s * (1.f / H);
            float rs = rsqrtf(s2 * (1.f / H) - m * m + 1e-5f);
            #pragma unroll
            for (int j = 0; j < 4; j++) {
                int n = lane + 32 * j;
                float y = g3[n] * (v[j] - m) * rs + be3[n];
                outE[(size_t)t * KNB * H + (size_t)r * H + n] = y;
            }
        }
    }
}

// ---------------------------------------------------------------------------
extern "C" void kernel_launch(void* const* d_in, const int* in_sizes, int n_in,
                              void* d_out, int out_size) {
    const float* hV    = (const float*)d_in[0];
    const float* hE    = (const float*)d_in[1];
    const int*   Eidx  = (const int*)  d_in[2];
    const float* maskV = (const float*)d_in[3];
    const float* matt  = (const float*)d_in[4];
    const float* W1    = (const float*)d_in[5];
    const float* b1    = (const float*)d_in[6];
    const float* W2    = (const float*)d_in[7];
    const float* b2    = (const float*)d_in[8];
    const float* W3    = (const float*)d_in[9];
    const float* b3    = (const float*)d_in[10];
    const float* W11   = (const float*)d_in[11];
    const float* b11   = (const float*)d_in[12];
    const float* W12   = (const float*)d_in[13];
    const float* b12   = (const float*)d_in[14];
    const float* W13   = (const float*)d_in[15];
    const float* b13   = (const float*)d_in[16];
    const float* g1    = (const float*)d_in[17];
    const float* be1   = (const float*)d_in[18];
    const float* g2    = (const float*)d_in[19];
    const float* be2   = (const float*)d_in[20];
    const float* g3    = (const float*)d_in[21];
    const float* be3   = (const float*)d_in[22];
    const float* W_in  = (const float*)d_in[23];
    const float* b_in  = (const float*)d_in[24];
    const float* W_out = (const float*)d_in[25];
    const float* b_out = (const float*)d_in[26];

    int ntok = in_sizes[3];   // B*L  (mask_V element count)

    size_t smemP = (size_t)(2 * H * H + 32 * H) * sizeof(float);
    size_t smemA = (size_t)(3 * KNB * H + 2 * H + KNB + 16) * sizeof(float);
    size_t smemB = (size_t)(32 * H + 32 * 512 + 64) * sizeof(float);
    size_t smemC = (size_t)(3 * KNB * H + H + 16) * sizeof(float);

    cudaFuncSetAttribute(k_pre,  cudaFuncAttributeMaxDynamicSharedMemorySize, (int)smemP);
    cudaFuncSetAttribute(k_node, cudaFuncAttributeMaxDynamicSharedMemorySize, (int)smemA);
    cudaFuncSetAttribute(k_ffn,  cudaFuncAttributeMaxDynamicSharedMemorySize, (int)smemB);
    cudaFuncSetAttribute(k_edge, cudaFuncAttributeMaxDynamicSharedMemorySize, (int)smemC);

    float* outV = (float*)d_out;
    float* outE = outV + (size_t)ntok * H;

    k_pre <<< ntok / 32, 128, smemP >>>(hV, W1, b1);
    k_node<<< ntok,      128, smemA >>>(hV, hE, Eidx, matt, W1, W2, b2, W3, b3, g1, be1);
    k_ffn <<< ntok / 32, 128, smemB >>>(maskV, W_in, b_in, W_out, b_out, g2, be2, W11, b11, outV);
    k_edge<<< ntok,      128, smemC >>>(hE, Eidx, W11, W12, b12, W13, b13, g3, be3, outE);
}